// round 14
// baseline (speedup 1.0000x reference)
#include <cuda_runtime.h>
#include <math_constants.h>
#include <cstdint>

#define BB 4096
#define DD 2048
#define PP 256
#define SS 64
#define CC 32
#define KP 8
#define BUCKET 256

// childlogits dynamic smem layout (floats):
//   Xs: 4 bufs x 64 tok x 36    Gs: 4 bufs x 32 d x 36    toks: 64 ints
#define XROW 36
#define XBUF (64 * XROW)            // floats per X buffer
#define GBUF (32 * XROW)            // floats per G buffer
#define CL_SMEM_BYTES ((4 * XBUF + 4 * GBUF) * 4 + 64 * 4)

// ---------------- scratch (device globals; no allocation) ----------------
__device__ float g_logits[BB * PP];                 // 4 MB
__device__ int   g_topidx[BB * KP];
__device__ int   g_child[BB * KP];
__device__ float g_G[(size_t)PP * DD * CC];         // 64 MB  [p][d][c]  (transposed)
__device__ float g_M[(size_t)PP * CC * DD];         // 64 MB  [p][c][d] (+0.1*W_rd col)
__device__ int   g_count[PP];
__device__ int   g_pairs[PP * BUCKET];

__device__ __forceinline__ unsigned s2u(const void* p) {
    return (unsigned)__cvta_generic_to_shared(p);
}
__device__ __forceinline__ void cp16(unsigned dst, const void* src) {
    asm volatile("cp.async.cg.shared.global [%0], [%1], 16;" :: "r"(dst), "l"(src));
}
#define CP_COMMIT() asm volatile("cp.async.commit_group;" ::: "memory")
#define CP_WAIT2()  asm volatile("cp.async.wait_group 2;" ::: "memory")

// ---------------- parent logits: [B,P] = X @ Wre^T + bre (double-buffered) ----------------
__global__ void __launch_bounds__(256) k_gemm_logits(const float* __restrict__ X,
                                                     const float* __restrict__ Wre,
                                                     const float* __restrict__ bre) {
    __shared__ float As[2][32][68];    // [buf][k][m]
    __shared__ float Bs[2][32][68];    // [buf][k][n]
    const int tid = threadIdx.x;
    const int n0b = blockIdx.x * 64;
    const int m0b = blockIdx.y * 64;
    const int n0 = (tid & 15) * 4;
    const int m0 = (tid >> 4) * 4;
    const int r0 = tid >> 3,          kq0 = tid & 7;
    const int r1 = (tid + 256) >> 3,  kq1 = (tid + 256) & 7;

    float acc[4][4];
#pragma unroll
    for (int i = 0; i < 4; i++)
#pragma unroll
        for (int j = 0; j < 4; j++) acc[i][j] = 0.f;

    {
        float4 a0 = *(const float4*)&X[(size_t)(m0b + r0) * DD + kq0 * 4];
        float4 a1 = *(const float4*)&X[(size_t)(m0b + r1) * DD + kq1 * 4];
        float4 b0 = *(const float4*)&Wre[(size_t)(n0b + r0) * DD + kq0 * 4];
        float4 b1 = *(const float4*)&Wre[(size_t)(n0b + r1) * DD + kq1 * 4];
        As[0][kq0 * 4 + 0][r0] = a0.x; As[0][kq0 * 4 + 1][r0] = a0.y;
        As[0][kq0 * 4 + 2][r0] = a0.z; As[0][kq0 * 4 + 3][r0] = a0.w;
        As[0][kq1 * 4 + 0][r1] = a1.x; As[0][kq1 * 4 + 1][r1] = a1.y;
        As[0][kq1 * 4 + 2][r1] = a1.z; As[0][kq1 * 4 + 3][r1] = a1.w;
        Bs[0][kq0 * 4 + 0][r0] = b0.x; Bs[0][kq0 * 4 + 1][r0] = b0.y;
        Bs[0][kq0 * 4 + 2][r0] = b0.z; Bs[0][kq0 * 4 + 3][r0] = b0.w;
        Bs[0][kq1 * 4 + 0][r1] = b1.x; Bs[0][kq1 * 4 + 1][r1] = b1.y;
        Bs[0][kq1 * 4 + 2][r1] = b1.z; Bs[0][kq1 * 4 + 3][r1] = b1.w;
    }
    __syncthreads();

    int cur = 0;
    for (int k0 = 32; k0 <= DD; k0 += 32) {
        float4 a0, a1, b0, b1;
        const bool more = (k0 < DD);
        if (more) {
            a0 = *(const float4*)&X[(size_t)(m0b + r0) * DD + k0 + kq0 * 4];
            a1 = *(const float4*)&X[(size_t)(m0b + r1) * DD + k0 + kq1 * 4];
            b0 = *(const float4*)&Wre[(size_t)(n0b + r0) * DD + k0 + kq0 * 4];
            b1 = *(const float4*)&Wre[(size_t)(n0b + r1) * DD + k0 + kq1 * 4];
        }
#pragma unroll 8
        for (int k = 0; k < 32; k++) {
            float4 a = *(const float4*)&As[cur][k][m0];
            float4 b = *(const float4*)&Bs[cur][k][n0];
            acc[0][0] += a.x * b.x; acc[0][1] += a.x * b.y; acc[0][2] += a.x * b.z; acc[0][3] += a.x * b.w;
            acc[1][0] += a.y * b.x; acc[1][1] += a.y * b.y; acc[1][2] += a.y * b.z; acc[1][3] += a.y * b.w;
            acc[2][0] += a.z * b.x; acc[2][1] += a.z * b.y; acc[2][2] += a.z * b.z; acc[2][3] += a.z * b.w;
            acc[3][0] += a.w * b.x; acc[3][1] += a.w * b.y; acc[3][2] += a.w * b.z; acc[3][3] += a.w * b.w;
        }
        if (more) {
            int nxt = cur ^ 1;
            As[nxt][kq0 * 4 + 0][r0] = a0.x; As[nxt][kq0 * 4 + 1][r0] = a0.y;
            As[nxt][kq0 * 4 + 2][r0] = a0.z; As[nxt][kq0 * 4 + 3][r0] = a0.w;
            As[nxt][kq1 * 4 + 0][r1] = a1.x; As[nxt][kq1 * 4 + 1][r1] = a1.y;
            As[nxt][kq1 * 4 + 2][r1] = a1.z; As[nxt][kq1 * 4 + 3][r1] = a1.w;
            Bs[nxt][kq0 * 4 + 0][r0] = b0.x; Bs[nxt][kq0 * 4 + 1][r0] = b0.y;
            Bs[nxt][kq0 * 4 + 2][r0] = b0.z; Bs[nxt][kq0 * 4 + 3][r0] = b0.w;
            Bs[nxt][kq1 * 4 + 0][r1] = b1.x; Bs[nxt][kq1 * 4 + 1][r1] = b1.y;
            Bs[nxt][kq1 * 4 + 2][r1] = b1.z; Bs[nxt][kq1 * 4 + 3][r1] = b1.w;
            __syncthreads();
            cur = nxt;
        }
    }
    float4 bv = *(const float4*)&bre[n0b + n0];
#pragma unroll
    for (int i = 0; i < 4; i++) {
        float4 o = make_float4(acc[i][0] + bv.x, acc[i][1] + bv.y,
                               acc[i][2] + bv.z, acc[i][3] + bv.w);
        *(float4*)&g_logits[(size_t)(m0b + m0 + i) * PP + n0b + n0] = o;
    }
}

// ---------------- top-8 per token + direct bucket append ----------------
__global__ void k_topk() {
    int gw = (blockIdx.x * blockDim.x + threadIdx.x) >> 5;
    int lane = threadIdx.x & 31;
    if (gw >= BB) return;
    const float* lg = g_logits + (size_t)gw * PP;
    float v[8];
    int id[8];
#pragma unroll
    for (int j = 0; j < 8; j++) {
        int p = j * 32 + lane;
        v[j] = lg[p];
        id[j] = p;
    }
    for (int it = 0; it < KP; it++) {
        float bv = v[0];
        int bi = id[0];
#pragma unroll
        for (int j = 1; j < 8; j++) {
            if (v[j] > bv || (v[j] == bv && id[j] < bi)) { bv = v[j]; bi = id[j]; }
        }
#pragma unroll
        for (int off = 16; off >= 1; off >>= 1) {
            float ov = __shfl_down_sync(0xffffffffu, bv, off);
            int   oi = __shfl_down_sync(0xffffffffu, bi, off);
            if (ov > bv || (ov == bv && oi < bi)) { bv = ov; bi = oi; }
        }
        bi = __shfl_sync(0xffffffffu, bi, 0);
        if (lane == 0) {
            g_topidx[gw * KP + it] = bi;
            int pos = atomicAdd(&g_count[bi], 1);
            g_pairs[bi * BUCKET + pos] = gw * KP + it;
        }
#pragma unroll
        for (int j = 0; j < 8; j++)
            if (id[j] == bi) v[j] = -CUDART_INF_F;
    }
}

// ---------------- G[p][d][c] = sum_s Wce[p][c][s] * Wdown[p][s][d]  (transposed store) ----------------
__global__ void __launch_bounds__(256) k_precompG(const float* __restrict__ Wdown,
                                                  const float* __restrict__ Wce) {
    __shared__ float Wd[32][260];   // [s][d]
    __shared__ float Ce[32][36];    // [s][c]
    const int p = blockIdx.x;
    const int d0b = blockIdx.y * 256;
    const int tid = threadIdx.x;
    const int lane = tid & 31;
    const int wid = tid >> 5;
    const int dl = (wid >> 2) * 128 + lane * 4;
    const int c0 = (wid & 3) * 8;

    if (blockIdx.y == 0 && tid == 0) g_count[p] = 0;

    float acc[4][8];
#pragma unroll
    for (int j = 0; j < 4; j++)
#pragma unroll
        for (int i = 0; i < 8; i++) acc[j][i] = 0.f;

    for (int s0 = 0; s0 < SS; s0 += 32) {
#pragma unroll
        for (int it = 0; it < 8; it++) {
            int l = tid + it * 256;
            int s = l >> 6, q = l & 63;
            *(float4*)&Wd[s][q * 4] =
                *(const float4*)&Wdown[((size_t)p * SS + s0 + s) * DD + d0b + q * 4];
        }
        {
            int c = tid >> 3, sq = tid & 7;
            float4 v = *(const float4*)&Wce[((size_t)p * CC + c) * SS + s0 + sq * 4];
            Ce[sq * 4 + 0][c] = v.x;
            Ce[sq * 4 + 1][c] = v.y;
            Ce[sq * 4 + 2][c] = v.z;
            Ce[sq * 4 + 3][c] = v.w;
        }
        __syncthreads();
#pragma unroll 4
        for (int s = 0; s < 32; s++) {
            float4 w   = *(const float4*)&Wd[s][dl];
            float4 cd0 = *(const float4*)&Ce[s][c0];
            float4 cd1 = *(const float4*)&Ce[s][c0 + 4];
            acc[0][0] += w.x * cd0.x; acc[0][1] += w.x * cd0.y; acc[0][2] += w.x * cd0.z; acc[0][3] += w.x * cd0.w;
            acc[0][4] += w.x * cd1.x; acc[0][5] += w.x * cd1.y; acc[0][6] += w.x * cd1.z; acc[0][7] += w.x * cd1.w;
            acc[1][0] += w.y * cd0.x; acc[1][1] += w.y * cd0.y; acc[1][2] += w.y * cd0.z; acc[1][3] += w.y * cd0.w;
            acc[1][4] += w.y * cd1.x; acc[1][5] += w.y * cd1.y; acc[1][6] += w.y * cd1.z; acc[1][7] += w.y * cd1.w;
            acc[2][0] += w.z * cd0.x; acc[2][1] += w.z * cd0.y; acc[2][2] += w.z * cd0.z; acc[2][3] += w.z * cd0.w;
            acc[2][4] += w.z * cd1.x; acc[2][5] += w.z * cd1.y; acc[2][6] += w.z * cd1.z; acc[2][7] += w.z * cd1.w;
            acc[3][0] += w.w * cd0.x; acc[3][1] += w.w * cd0.y; acc[3][2] += w.w * cd0.z; acc[3][3] += w.w * cd0.w;
            acc[3][4] += w.w * cd1.x; acc[3][5] += w.w * cd1.y; acc[3][6] += w.w * cd1.z; acc[3][7] += w.w * cd1.w;
        }
        __syncthreads();
    }
#pragma unroll
    for (int u = 0; u < 4; u++) {
        size_t row = ((size_t)p * DD + d0b + dl + u) * CC;
        *(float4*)&g_G[row + c0]     = make_float4(acc[u][0], acc[u][1], acc[u][2], acc[u][3]);
        *(float4*)&g_G[row + c0 + 4] = make_float4(acc[u][4], acc[u][5], acc[u][6], acc[u][7]);
    }
}

// ---------------- M'[p][c][d] = sum_s Wup[p][d][s]*Wcd[p][s][c] + 0.1*Wrd[d][p] ----------------
__global__ void __launch_bounds__(256) k_precompM(const float* __restrict__ Wup,
                                                  const float* __restrict__ Wcd,
                                                  const float* __restrict__ Wrd) {
    __shared__ float Wu[32][260];   // [s][d]
    __shared__ float Cd[32][36];    // [s][c]
    __shared__ float wrs[256];
    const int p = blockIdx.x;
    const int d0b = blockIdx.y * 256;
    const int tid = threadIdx.x;
    const int lane = tid & 31;
    const int wid = tid >> 5;
    const int dl = (wid >> 2) * 128 + lane * 4;
    const int c0 = (wid & 3) * 8;

    wrs[tid] = 0.1f * Wrd[(size_t)(d0b + tid) * PP + p];

    float acc[4][8];
#pragma unroll
    for (int j = 0; j < 4; j++)
#pragma unroll
        for (int i = 0; i < 8; i++) acc[j][i] = 0.f;

    for (int s0 = 0; s0 < SS; s0 += 32) {
#pragma unroll
        for (int it = 0; it < 8; it++) {
            int l = tid + it * 256;
            int d = l >> 3, sq = l & 7;
            float4 v = *(const float4*)&Wup[((size_t)p * DD + d0b + d) * SS + s0 + sq * 4];
            Wu[sq * 4 + 0][d] = v.x;
            Wu[sq * 4 + 1][d] = v.y;
            Wu[sq * 4 + 2][d] = v.z;
            Wu[sq * 4 + 3][d] = v.w;
        }
        {
            int s = tid >> 3, q = tid & 7;
            *(float4*)&Cd[s][q * 4] =
                *(const float4*)&Wcd[((size_t)p * SS + s0 + s) * CC + q * 4];
        }
        __syncthreads();
#pragma unroll 4
        for (int s = 0; s < 32; s++) {
            float4 w   = *(const float4*)&Wu[s][dl];
            float4 cd0 = *(const float4*)&Cd[s][c0];
            float4 cd1 = *(const float4*)&Cd[s][c0 + 4];
            acc[0][0] += w.x * cd0.x; acc[0][1] += w.x * cd0.y; acc[0][2] += w.x * cd0.z; acc[0][3] += w.x * cd0.w;
            acc[0][4] += w.x * cd1.x; acc[0][5] += w.x * cd1.y; acc[0][6] += w.x * cd1.z; acc[0][7] += w.x * cd1.w;
            acc[1][0] += w.y * cd0.x; acc[1][1] += w.y * cd0.y; acc[1][2] += w.y * cd0.z; acc[1][3] += w.y * cd0.w;
            acc[1][4] += w.y * cd1.x; acc[1][5] += w.y * cd1.y; acc[1][6] += w.y * cd1.z; acc[1][7] += w.y * cd1.w;
            acc[2][0] += w.z * cd0.x; acc[2][1] += w.z * cd0.y; acc[2][2] += w.z * cd0.z; acc[2][3] += w.z * cd0.w;
            acc[2][4] += w.z * cd1.x; acc[2][5] += w.z * cd1.y; acc[2][6] += w.z * cd1.z; acc[2][7] += w.z * cd1.w;
            acc[3][0] += w.w * cd0.x; acc[3][1] += w.w * cd0.y; acc[3][2] += w.w * cd0.z; acc[3][3] += w.w * cd0.w;
            acc[3][4] += w.w * cd1.x; acc[3][5] += w.w * cd1.y; acc[3][6] += w.w * cd1.z; acc[3][7] += w.w * cd1.w;
        }
        __syncthreads();
    }
#pragma unroll
    for (int i = 0; i < 8; i++) {
        size_t row = ((size_t)p * CC + c0 + i) * DD + d0b + dl;
        *(float4*)&g_M[row] = make_float4(acc[0][i] + wrs[dl + 0], acc[1][i] + wrs[dl + 1],
                                          acc[2][i] + wrs[dl + 2], acc[3][i] + wrs[dl + 3]);
    }
}

// ---------------- per-parent child logits + argmax (G is [p][d][c]) ----------------
// grid (P, 2), 256 threads, DYNAMIC smem (55.5KB). tile 64 tok x 32 c; thread: 2 tok x 4 c.
// 32-d chunks, cp.async 4-stage ring, prefetch depth 2 (issue k+2, wait_group 2).
__global__ void __launch_bounds__(256) k_childlogits(const float* __restrict__ X,
                                                     const float* __restrict__ bce) {
    extern __shared__ __align__(16) float dyn[];
    float* Xs = dyn;                        // [4][64][XROW]
    float* Gs = dyn + 4 * XBUF;             // [4][32][XROW]
    int*  toks = (int*)(dyn + 4 * XBUF + 4 * GBUF);   // [64]
    const int p = blockIdx.x;
    const int base = p * BUCKET;
    const int n = g_count[p];
    const int tid = threadIdx.x;
    const int r  = tid >> 3;          // 0..31 : token rows r, r+32; also G d-row & X load row
    const int q  = tid & 7;
    const int qc = q * 4;
    float bc[4];
#pragma unroll
    for (int i = 0; i < 4; i++) bc[i] = bce[p * CC + qc + i];

    const unsigned xsA = s2u(&Xs[r * XROW + qc]);
    const unsigned xsB = s2u(&Xs[(r + 32) * XROW + qc]);
    const unsigned gsA = s2u(&Gs[r * XROW + qc]);
    const unsigned XS_BUF = XBUF * 4;       // bytes
    const unsigned GS_BUF = GBUF * 4;       // bytes
    const float* grow = &g_G[((size_t)p * DD + r) * CC + qc];

    for (int t0 = blockIdx.y * 64; t0 < n; t0 += 128) {
        if (tid < 64) toks[tid] = (t0 + tid < n) ? g_pairs[base + t0 + tid] : -1;
        __syncthreads();

        const int pi0 = toks[r];
        const int pi1 = toks[r + 32];
        const float* xrow0 = &X[(size_t)((pi0 >= 0 ? pi0 : 0) >> 3) * DD + qc];
        const float* xrow1 = &X[(size_t)((pi1 >= 0 ? pi1 : 0) >> 3) * DD + qc];

        float acc[2][4];
#pragma unroll
        for (int j = 0; j < 2; j++)
#pragma unroll
            for (int i = 0; i < 4; i++) acc[j][i] = 0.f;

        // prologue: chunks 0,1 -> bufs 0,1 (two groups in flight)
        cp16(xsA, xrow0);
        cp16(xsB, xrow1);
        cp16(gsA, grow);
        CP_COMMIT();
        cp16(xsA + XS_BUF, xrow0 + 32);
        cp16(xsB + XS_BUF, xrow1 + 32);
        cp16(gsA + GS_BUF, grow + (size_t)32 * CC);
        CP_COMMIT();

        int nb = 2;                 // buffer for chunk k+2
        for (int k = 0; k < 64; k++) {
            if (k < 62) {
                const int d0 = (k + 2) * 32;
                cp16(xsA + nb * XS_BUF, xrow0 + d0);
                cp16(xsB + nb * XS_BUF, xrow1 + d0);
                cp16(gsA + nb * GS_BUF, grow + (size_t)d0 * CC);
                if (++nb == 4) nb = 0;
            }
            CP_COMMIT();
            CP_WAIT2();             // chunk k complete (k+1, k+2 may be in flight)
            __syncthreads();
            const int cb = (k & 3);
            const float* xb = &Xs[cb * XBUF];
            const float* gb = &Gs[cb * GBUF];
#pragma unroll
            for (int d4 = 0; d4 < 32; d4 += 4) {
                float4 xv0 = *(const float4*)&xb[r * XROW + d4];
                float4 xv1 = *(const float4*)&xb[(r + 32) * XROW + d4];
                float4 g0 = *(const float4*)&gb[(d4 + 0) * XROW + qc];
                float4 g1 = *(const float4*)&gb[(d4 + 1) * XROW + qc];
                float4 g2 = *(const float4*)&gb[(d4 + 2) * XROW + qc];
                float4 g3 = *(const float4*)&gb[(d4 + 3) * XROW + qc];
                acc[0][0] += xv0.x * g0.x + xv0.y * g1.x + xv0.z * g2.x + xv0.w * g3.x;
                acc[0][1] += xv0.x * g0.y + xv0.y * g1.y + xv0.z * g2.y + xv0.w * g3.y;
                acc[0][2] += xv0.x * g0.z + xv0.y * g1.z + xv0.z * g2.z + xv0.w * g3.z;
                acc[0][3] += xv0.x * g0.w + xv0.y * g1.w + xv0.z * g2.w + xv0.w * g3.w;
                acc[1][0] += xv1.x * g0.x + xv1.y * g1.x + xv1.z * g2.x + xv1.w * g3.x;
                acc[1][1] += xv1.x * g0.y + xv1.y * g1.y + xv1.z * g2.y + xv1.w * g3.y;
                acc[1][2] += xv1.x * g0.z + xv1.y * g1.z + xv1.z * g2.z + xv1.w * g3.z;
                acc[1][3] += xv1.x * g0.w + xv1.y * g1.w + xv1.z * g2.w + xv1.w * g3.w;
            }
        }

        // argmax over 32 c per token (tie -> lower index), width-8 shuffle groups
#pragma unroll
        for (int j = 0; j < 2; j++) {
            float bv = acc[j][0] + bc[0];
            int bi = qc;
#pragma unroll
            for (int i = 1; i < 4; i++) {
                float v = acc[j][i] + bc[i];
                if (v > bv) { bv = v; bi = qc + i; }
            }
#pragma unroll
            for (int off = 4; off >= 1; off >>= 1) {
                float ov = __shfl_down_sync(0xffffffffu, bv, off, 8);
                int   oi = __shfl_down_sync(0xffffffffu, bi, off, 8);
                if (ov > bv || (ov == bv && oi < bi)) { bv = ov; bi = oi; }
            }
            if (q == 0) {
                int pi = (j == 0) ? pi0 : pi1;
                if (pi >= 0) g_child[pi] = bi;
            }
        }
        __syncthreads();   // protect toks/smem before next tile
    }
}

// ---------------- decode: out = bias + sum_k M'[p_k][c_k] ----------------
__global__ void k_decode(const float* __restrict__ dbias, float* __restrict__ out) {
    const int b = blockIdx.x;
    __shared__ int sp[KP], sc[KP];
    const int tid = threadIdx.x;
    if (tid < KP) {
        sp[tid] = g_topidx[b * KP + tid];
        sc[tid] = g_child[b * KP + tid];
    }
    __syncthreads();
    size_t rowbase[KP];
#pragma unroll
    for (int k = 0; k < KP; k++)
        rowbase[k] = ((size_t)sp[k] * CC + sc[k]) * DD;
#pragma unroll
    for (int it = 0; it < 2; it++) {
        int d = (tid + it * 256) * 4;
        float4 a = *(const float4*)&dbias[d];
#pragma unroll
        for (int k = 0; k < KP; k++) {
            float4 m = *(const float4*)&g_M[rowbase[k] + d];
            a.x += m.x; a.y += m.y; a.z += m.z; a.w += m.w;
        }
        *(float4*)&out[(size_t)b * DD + d] = a;
    }
}

// ---------------- launch (childlogits stays at launch #4 -> ncu capture window) ----------------
extern "C" void kernel_launch(void* const* d_in, const int* in_sizes, int n_in,
                              void* d_out, int out_size) {
    const float* x      = (const float*)d_in[0];
    const float* W_re   = (const float*)d_in[1];
    const float* b_re   = (const float*)d_in[2];
    const float* W_rd   = (const float*)d_in[3];
    const float* W_down = (const float*)d_in[4];
    const float* W_up   = (const float*)d_in[5];
    const float* W_ce   = (const float*)d_in[6];
    const float* b_ce   = (const float*)d_in[7];
    const float* W_cd   = (const float*)d_in[8];
    const float* dbias  = (const float*)d_in[9];
    float* out = (float*)d_out;

    cudaFuncSetAttribute(k_childlogits,
                         cudaFuncAttributeMaxDynamicSharedMemorySize, CL_SMEM_BYTES);

    k_precompG<<<dim3(PP, DD / 256), 256>>>(W_down, W_ce);     // also zeroes g_count
    k_gemm_logits<<<dim3(PP / 64, BB / 64), 256>>>(x, W_re, b_re);
    k_topk<<<(BB * 32) / 256, 256>>>();
    k_childlogits<<<dim3(PP, 2), 256, CL_SMEM_BYTES>>>(x, b_ce);   // <- captured launch #4
    k_precompM<<<dim3(PP, DD / 256), 256>>>(W_up, W_cd, W_rd);
    k_decode<<<BB, 256>>>(dbias, out);
}

// round 16
// speedup vs baseline: 1.0215x; 1.0215x over previous
#include <cuda_runtime.h>
#include <math_constants.h>
#include <cstdint>

#define BB 4096
#define DD 2048
#define PP 256
#define SS 64
#define CC 32
#define KP 8
#define BUCKET 256

// ---------------- scratch (device globals; no allocation) ----------------
__device__ float g_logits[BB * PP];                 // 4 MB
__device__ int   g_topidx[BB * KP];
__device__ int   g_child[BB * KP];
__device__ float g_G[(size_t)PP * DD * CC];         // 64 MB  [p][d][c]  (transposed)
__device__ float g_M[(size_t)PP * CC * DD];         // 64 MB  [p][c][d] (+0.1*W_rd col)
__device__ int   g_count[PP];
__device__ int   g_pairs[PP * BUCKET];

// ---------------- parent logits: [B,P] = X @ Wre^T + bre (double-buffered) ----------------
__global__ void __launch_bounds__(256) k_gemm_logits(const float* __restrict__ X,
                                                     const float* __restrict__ Wre,
                                                     const float* __restrict__ bre) {
    __shared__ float As[2][32][68];    // [buf][k][m]
    __shared__ float Bs[2][32][68];    // [buf][k][n]
    const int tid = threadIdx.x;
    const int n0b = blockIdx.x * 64;
    const int m0b = blockIdx.y * 64;
    const int n0 = (tid & 15) * 4;
    const int m0 = (tid >> 4) * 4;
    const int r0 = tid >> 3,          kq0 = tid & 7;
    const int r1 = (tid + 256) >> 3,  kq1 = (tid + 256) & 7;

    float acc[4][4];
#pragma unroll
    for (int i = 0; i < 4; i++)
#pragma unroll
        for (int j = 0; j < 4; j++) acc[i][j] = 0.f;

    {
        float4 a0 = *(const float4*)&X[(size_t)(m0b + r0) * DD + kq0 * 4];
        float4 a1 = *(const float4*)&X[(size_t)(m0b + r1) * DD + kq1 * 4];
        float4 b0 = *(const float4*)&Wre[(size_t)(n0b + r0) * DD + kq0 * 4];
        float4 b1 = *(const float4*)&Wre[(size_t)(n0b + r1) * DD + kq1 * 4];
        As[0][kq0 * 4 + 0][r0] = a0.x; As[0][kq0 * 4 + 1][r0] = a0.y;
        As[0][kq0 * 4 + 2][r0] = a0.z; As[0][kq0 * 4 + 3][r0] = a0.w;
        As[0][kq1 * 4 + 0][r1] = a1.x; As[0][kq1 * 4 + 1][r1] = a1.y;
        As[0][kq1 * 4 + 2][r1] = a1.z; As[0][kq1 * 4 + 3][r1] = a1.w;
        Bs[0][kq0 * 4 + 0][r0] = b0.x; Bs[0][kq0 * 4 + 1][r0] = b0.y;
        Bs[0][kq0 * 4 + 2][r0] = b0.z; Bs[0][kq0 * 4 + 3][r0] = b0.w;
        Bs[0][kq1 * 4 + 0][r1] = b1.x; Bs[0][kq1 * 4 + 1][r1] = b1.y;
        Bs[0][kq1 * 4 + 2][r1] = b1.z; Bs[0][kq1 * 4 + 3][r1] = b1.w;
    }
    __syncthreads();

    int cur = 0;
    for (int k0 = 32; k0 <= DD; k0 += 32) {
        float4 a0, a1, b0, b1;
        const bool more = (k0 < DD);
        if (more) {
            a0 = *(const float4*)&X[(size_t)(m0b + r0) * DD + k0 + kq0 * 4];
            a1 = *(const float4*)&X[(size_t)(m0b + r1) * DD + k0 + kq1 * 4];
            b0 = *(const float4*)&Wre[(size_t)(n0b + r0) * DD + k0 + kq0 * 4];
            b1 = *(const float4*)&Wre[(size_t)(n0b + r1) * DD + k0 + kq1 * 4];
        }
#pragma unroll 8
        for (int k = 0; k < 32; k++) {
            float4 a = *(const float4*)&As[cur][k][m0];
            float4 b = *(const float4*)&Bs[cur][k][n0];
            acc[0][0] += a.x * b.x; acc[0][1] += a.x * b.y; acc[0][2] += a.x * b.z; acc[0][3] += a.x * b.w;
            acc[1][0] += a.y * b.x; acc[1][1] += a.y * b.y; acc[1][2] += a.y * b.z; acc[1][3] += a.y * b.w;
            acc[2][0] += a.z * b.x; acc[2][1] += a.z * b.y; acc[2][2] += a.z * b.z; acc[2][3] += a.z * b.w;
            acc[3][0] += a.w * b.x; acc[3][1] += a.w * b.y; acc[3][2] += a.w * b.z; acc[3][3] += a.w * b.w;
        }
        if (more) {
            int nxt = cur ^ 1;
            As[nxt][kq0 * 4 + 0][r0] = a0.x; As[nxt][kq0 * 4 + 1][r0] = a0.y;
            As[nxt][kq0 * 4 + 2][r0] = a0.z; As[nxt][kq0 * 4 + 3][r0] = a0.w;
            As[nxt][kq1 * 4 + 0][r1] = a1.x; As[nxt][kq1 * 4 + 1][r1] = a1.y;
            As[nxt][kq1 * 4 + 2][r1] = a1.z; As[nxt][kq1 * 4 + 3][r1] = a1.w;
            Bs[nxt][kq0 * 4 + 0][r0] = b0.x; Bs[nxt][kq0 * 4 + 1][r0] = b0.y;
            Bs[nxt][kq0 * 4 + 2][r0] = b0.z; Bs[nxt][kq0 * 4 + 3][r0] = b0.w;
            Bs[nxt][kq1 * 4 + 0][r1] = b1.x; Bs[nxt][kq1 * 4 + 1][r1] = b1.y;
            Bs[nxt][kq1 * 4 + 2][r1] = b1.z; Bs[nxt][kq1 * 4 + 3][r1] = b1.w;
            __syncthreads();
            cur = nxt;
        }
    }
    float4 bv = *(const float4*)&bre[n0b + n0];
#pragma unroll
    for (int i = 0; i < 4; i++) {
        float4 o = make_float4(acc[i][0] + bv.x, acc[i][1] + bv.y,
                               acc[i][2] + bv.z, acc[i][3] + bv.w);
        *(float4*)&g_logits[(size_t)(m0b + m0 + i) * PP + n0b + n0] = o;
    }
}

// ---------------- top-8 per token + direct bucket append ----------------
__global__ void k_topk() {
    int gw = (blockIdx.x * blockDim.x + threadIdx.x) >> 5;
    int lane = threadIdx.x & 31;
    if (gw >= BB) return;
    const float* lg = g_logits + (size_t)gw * PP;
    float v[8];
    int id[8];
#pragma unroll
    for (int j = 0; j < 8; j++) {
        int p = j * 32 + lane;
        v[j] = lg[p];
        id[j] = p;
    }
    for (int it = 0; it < KP; it++) {
        float bv = v[0];
        int bi = id[0];
#pragma unroll
        for (int j = 1; j < 8; j++) {
            if (v[j] > bv || (v[j] == bv && id[j] < bi)) { bv = v[j]; bi = id[j]; }
        }
#pragma unroll
        for (int off = 16; off >= 1; off >>= 1) {
            float ov = __shfl_down_sync(0xffffffffu, bv, off);
            int   oi = __shfl_down_sync(0xffffffffu, bi, off);
            if (ov > bv || (ov == bv && oi < bi)) { bv = ov; bi = oi; }
        }
        bi = __shfl_sync(0xffffffffu, bi, 0);
        if (lane == 0) {
            g_topidx[gw * KP + it] = bi;
            int pos = atomicAdd(&g_count[bi], 1);
            g_pairs[bi * BUCKET + pos] = gw * KP + it;
        }
#pragma unroll
        for (int j = 0; j < 8; j++)
            if (id[j] == bi) v[j] = -CUDART_INF_F;
    }
}

// ---------------- fused precomp: y<8 -> G tile, y>=8 -> M tile ----------------
// G[p][d][c] = sum_s Wce[p][c][s] * Wdown[p][s][d]     (transposed store)
// M'[p][c][d] = sum_s Wup[p][d][s]*Wcd[p][s][c] + 0.1*Wrd[d][p]
__global__ void __launch_bounds__(256) k_precompGM(const float* __restrict__ Wdown,
                                                   const float* __restrict__ Wce,
                                                   const float* __restrict__ Wup,
                                                   const float* __restrict__ Wcd,
                                                   const float* __restrict__ Wrd) {
    __shared__ float Wbuf[32][260];   // [s][d]
    __shared__ float Cbuf[32][36];    // [s][c]
    __shared__ float wrs[256];
    const int p = blockIdx.x;
    const int tid = threadIdx.x;
    const int lane = tid & 31;
    const int wid = tid >> 5;
    const int dl = (wid >> 2) * 128 + lane * 4;
    const int c0 = (wid & 3) * 8;

    float acc[4][8];
#pragma unroll
    for (int j = 0; j < 4; j++)
#pragma unroll
        for (int i = 0; i < 8; i++) acc[j][i] = 0.f;

    if (blockIdx.y < 8) {
        // ---------- G path ----------
        const int d0b = blockIdx.y * 256;
        if (blockIdx.y == 0 && tid == 0) g_count[p] = 0;

        for (int s0 = 0; s0 < SS; s0 += 32) {
#pragma unroll
            for (int it = 0; it < 8; it++) {
                int l = tid + it * 256;
                int s = l >> 6, q = l & 63;
                *(float4*)&Wbuf[s][q * 4] =
                    *(const float4*)&Wdown[((size_t)p * SS + s0 + s) * DD + d0b + q * 4];
            }
            {
                int c = tid >> 3, sq = tid & 7;
                float4 v = *(const float4*)&Wce[((size_t)p * CC + c) * SS + s0 + sq * 4];
                Cbuf[sq * 4 + 0][c] = v.x;
                Cbuf[sq * 4 + 1][c] = v.y;
                Cbuf[sq * 4 + 2][c] = v.z;
                Cbuf[sq * 4 + 3][c] = v.w;
            }
            __syncthreads();
#pragma unroll 4
            for (int s = 0; s < 32; s++) {
                float4 w   = *(const float4*)&Wbuf[s][dl];
                float4 cd0 = *(const float4*)&Cbuf[s][c0];
                float4 cd1 = *(const float4*)&Cbuf[s][c0 + 4];
                acc[0][0] += w.x * cd0.x; acc[0][1] += w.x * cd0.y; acc[0][2] += w.x * cd0.z; acc[0][3] += w.x * cd0.w;
                acc[0][4] += w.x * cd1.x; acc[0][5] += w.x * cd1.y; acc[0][6] += w.x * cd1.z; acc[0][7] += w.x * cd1.w;
                acc[1][0] += w.y * cd0.x; acc[1][1] += w.y * cd0.y; acc[1][2] += w.y * cd0.z; acc[1][3] += w.y * cd0.w;
                acc[1][4] += w.y * cd1.x; acc[1][5] += w.y * cd1.y; acc[1][6] += w.y * cd1.z; acc[1][7] += w.y * cd1.w;
                acc[2][0] += w.z * cd0.x; acc[2][1] += w.z * cd0.y; acc[2][2] += w.z * cd0.z; acc[2][3] += w.z * cd0.w;
                acc[2][4] += w.z * cd1.x; acc[2][5] += w.z * cd1.y; acc[2][6] += w.z * cd1.z; acc[2][7] += w.z * cd1.w;
                acc[3][0] += w.w * cd0.x; acc[3][1] += w.w * cd0.y; acc[3][2] += w.w * cd0.z; acc[3][3] += w.w * cd0.w;
                acc[3][4] += w.w * cd1.x; acc[3][5] += w.w * cd1.y; acc[3][6] += w.w * cd1.z; acc[3][7] += w.w * cd1.w;
            }
            __syncthreads();
        }
        // store transposed: g_G[p][d][c]
#pragma unroll
        for (int u = 0; u < 4; u++) {
            size_t row = ((size_t)p * DD + d0b + dl + u) * CC;
            *(float4*)&g_G[row + c0]     = make_float4(acc[u][0], acc[u][1], acc[u][2], acc[u][3]);
            *(float4*)&g_G[row + c0 + 4] = make_float4(acc[u][4], acc[u][5], acc[u][6], acc[u][7]);
        }
    } else {
        // ---------- M path ----------
        const int d0b = (blockIdx.y - 8) * 256;
        wrs[tid] = 0.1f * Wrd[(size_t)(d0b + tid) * PP + p];

        for (int s0 = 0; s0 < SS; s0 += 32) {
#pragma unroll
            for (int it = 0; it < 8; it++) {
                int l = tid + it * 256;
                int d = l >> 3, sq = l & 7;
                float4 v = *(const float4*)&Wup[((size_t)p * DD + d0b + d) * SS + s0 + sq * 4];
                Wbuf[sq * 4 + 0][d] = v.x;
                Wbuf[sq * 4 + 1][d] = v.y;
                Wbuf[sq * 4 + 2][d] = v.z;
                Wbuf[sq * 4 + 3][d] = v.w;
            }
            {
                int s = tid >> 3, q = tid & 7;
                *(float4*)&Cbuf[s][q * 4] =
                    *(const float4*)&Wcd[((size_t)p * SS + s0 + s) * CC + q * 4];
            }
            __syncthreads();
#pragma unroll 4
            for (int s = 0; s < 32; s++) {
                float4 w   = *(const float4*)&Wbuf[s][dl];
                float4 cd0 = *(const float4*)&Cbuf[s][c0];
                float4 cd1 = *(const float4*)&Cbuf[s][c0 + 4];
                acc[0][0] += w.x * cd0.x; acc[0][1] += w.x * cd0.y; acc[0][2] += w.x * cd0.z; acc[0][3] += w.x * cd0.w;
                acc[0][4] += w.x * cd1.x; acc[0][5] += w.x * cd1.y; acc[0][6] += w.x * cd1.z; acc[0][7] += w.x * cd1.w;
                acc[1][0] += w.y * cd0.x; acc[1][1] += w.y * cd0.y; acc[1][2] += w.y * cd0.z; acc[1][3] += w.y * cd0.w;
                acc[1][4] += w.y * cd1.x; acc[1][5] += w.y * cd1.y; acc[1][6] += w.y * cd1.z; acc[1][7] += w.y * cd1.w;
                acc[2][0] += w.z * cd0.x; acc[2][1] += w.z * cd0.y; acc[2][2] += w.z * cd0.z; acc[2][3] += w.z * cd0.w;
                acc[2][4] += w.z * cd1.x; acc[2][5] += w.z * cd1.y; acc[2][6] += w.z * cd1.z; acc[2][7] += w.z * cd1.w;
                acc[3][0] += w.w * cd0.x; acc[3][1] += w.w * cd0.y; acc[3][2] += w.w * cd0.z; acc[3][3] += w.w * cd0.w;
                acc[3][4] += w.w * cd1.x; acc[3][5] += w.w * cd1.y; acc[3][6] += w.w * cd1.z; acc[3][7] += w.w * cd1.w;
            }
            __syncthreads();
        }
#pragma unroll
        for (int i = 0; i < 8; i++) {
            size_t row = ((size_t)p * CC + c0 + i) * DD + d0b + dl;
            *(float4*)&g_M[row] = make_float4(acc[0][i] + wrs[dl + 0], acc[1][i] + wrs[dl + 1],
                                              acc[2][i] + wrs[dl + 2], acc[3][i] + wrs[dl + 3]);
        }
    }
}

// ---------------- per-parent child logits + argmax (G is [p][d][c]) ----------------
// grid (P, 2), 256 threads. tile 64 tok x 32 c; thread: 2 tok (r, r+32) x 4 c.
// 32-d chunks, double-buffered smem + register prefetch, one sync per chunk. (R10 proven)
__global__ void __launch_bounds__(256) k_childlogits(const float* __restrict__ X,
                                                     const float* __restrict__ bce) {
    __shared__ float Xs[2][64][36];   // [buf][tok][d]
    __shared__ float Gs[2][32][36];   // [buf][d][c]
    __shared__ int toks[64];
    const int p = blockIdx.x;
    const int base = p * BUCKET;
    const int n = g_count[p];
    const int tid = threadIdx.x;
    const int r  = tid >> 3;          // 0..31 : token rows r and r+32; also G d-row
    const int q  = tid & 7;
    const int qc = q * 4;             // load column offset; also this thread's c0
    float bc[4];
#pragma unroll
    for (int i = 0; i < 4; i++) bc[i] = bce[p * CC + qc + i];

    for (int t0 = blockIdx.y * 64; t0 < n; t0 += 128) {
        if (tid < 64) toks[tid] = (t0 + tid < n) ? g_pairs[base + t0 + tid] : -1;
        __syncthreads();

        float acc[2][4];
#pragma unroll
        for (int j = 0; j < 2; j++)
#pragma unroll
            for (int i = 0; i < 4; i++) acc[j][i] = 0.f;

        const int pi0 = toks[r];
        const int pi1 = toks[r + 32];
        const float* xrow0 = (pi0 >= 0) ? &X[(size_t)(pi0 >> 3) * DD] : 0;
        const float* xrow1 = (pi1 >= 0) ? &X[(size_t)(pi1 >> 3) * DD] : 0;
        const float* grow  = &g_G[((size_t)p * DD + r) * CC + qc];

        // prologue: chunk 0 -> buf 0
        {
            float4 z = make_float4(0.f, 0.f, 0.f, 0.f);
            float4 xa0 = xrow0 ? *(const float4*)&xrow0[qc] : z;
            float4 xa1 = xrow1 ? *(const float4*)&xrow1[qc] : z;
            float4 ga  = *(const float4*)&grow[0];
            *(float4*)&Xs[0][r][qc]      = xa0;
            *(float4*)&Xs[0][r + 32][qc] = xa1;
            *(float4*)&Gs[0][r][qc]      = ga;
        }
        __syncthreads();

        int cur = 0;
        for (int d0 = 32; d0 <= DD; d0 += 32) {
            float4 xa0, xa1, ga;
            const bool more = (d0 < DD);
            if (more) {
                float4 z = make_float4(0.f, 0.f, 0.f, 0.f);
                xa0 = xrow0 ? *(const float4*)&xrow0[d0 + qc] : z;
                xa1 = xrow1 ? *(const float4*)&xrow1[d0 + qc] : z;
                ga  = *(const float4*)&grow[(size_t)d0 * CC];
            }
#pragma unroll
            for (int d4 = 0; d4 < 32; d4 += 4) {
                float4 xv0 = *(const float4*)&Xs[cur][r][d4];
                float4 xv1 = *(const float4*)&Xs[cur][r + 32][d4];
                float4 g0 = *(const float4*)&Gs[cur][d4 + 0][qc];
                float4 g1 = *(const float4*)&Gs[cur][d4 + 1][qc];
                float4 g2 = *(const float4*)&Gs[cur][d4 + 2][qc];
                float4 g3 = *(const float4*)&Gs[cur][d4 + 3][qc];
                acc[0][0] += xv0.x * g0.x + xv0.y * g1.x + xv0.z * g2.x + xv0.w * g3.x;
                acc[0][1] += xv0.x * g0.y + xv0.y * g1.y + xv0.z * g2.y + xv0.w * g3.y;
                acc[0][2] += xv0.x * g0.z + xv0.y * g1.z + xv0.z * g2.z + xv0.w * g3.z;
                acc[0][3] += xv0.x * g0.w + xv0.y * g1.w + xv0.z * g2.w + xv0.w * g3.w;
                acc[1][0] += xv1.x * g0.x + xv1.y * g1.x + xv1.z * g2.x + xv1.w * g3.x;
                acc[1][1] += xv1.x * g0.y + xv1.y * g1.y + xv1.z * g2.y + xv1.w * g3.y;
                acc[1][2] += xv1.x * g0.z + xv1.y * g1.z + xv1.z * g2.z + xv1.w * g3.z;
                acc[1][3] += xv1.x * g0.w + xv1.y * g1.w + xv1.z * g2.w + xv1.w * g3.w;
            }
            if (more) {
                int nxt = cur ^ 1;
                *(float4*)&Xs[nxt][r][qc]      = xa0;
                *(float4*)&Xs[nxt][r + 32][qc] = xa1;
                *(float4*)&Gs[nxt][r][qc]      = ga;
                __syncthreads();
                cur = nxt;
            }
        }

        // argmax over 32 c per token (tie -> lower index), width-8 shuffle groups
#pragma unroll
        for (int j = 0; j < 2; j++) {
            float bv = acc[j][0] + bc[0];
            int bi = qc;
#pragma unroll
            for (int i = 1; i < 4; i++) {
                float v = acc[j][i] + bc[i];
                if (v > bv) { bv = v; bi = qc + i; }
            }
#pragma unroll
            for (int off = 4; off >= 1; off >>= 1) {
                float ov = __shfl_down_sync(0xffffffffu, bv, off, 8);
                int   oi = __shfl_down_sync(0xffffffffu, bi, off, 8);
                if (ov > bv || (ov == bv && oi < bi)) { bv = ov; bi = oi; }
            }
            if (q == 0) {
                int pi = (j == 0) ? pi0 : pi1;
                if (pi >= 0) g_child[pi] = bi;
            }
        }
        __syncthreads();   // protect toks/smem before next tile
    }
}

// ---------------- decode: out = bias + sum_k M'[p_k][c_k] ----------------
__global__ void k_decode(const float* __restrict__ dbias, float* __restrict__ out) {
    const int b = blockIdx.x;
    __shared__ int sp[KP], sc[KP];
    const int tid = threadIdx.x;
    if (tid < KP) {
        sp[tid] = g_topidx[b * KP + tid];
        sc[tid] = g_child[b * KP + tid];
    }
    __syncthreads();
    size_t rowbase[KP];
#pragma unroll
    for (int k = 0; k < KP; k++)
        rowbase[k] = ((size_t)sp[k] * CC + sc[k]) * DD;
#pragma unroll
    for (int it = 0; it < 2; it++) {
        int d = (tid + it * 256) * 4;
        float4 a = *(const float4*)&dbias[d];
#pragma unroll
        for (int k = 0; k < KP; k++) {
            float4 m = *(const float4*)&g_M[rowbase[k] + d];
            a.x += m.x; a.y += m.y; a.z += m.z; a.w += m.w;
        }
        *(float4*)&out[(size_t)b * DD + d] = a;
    }
}

// ---------------- launch (childlogits stays at launch #4 -> ncu capture window) ----------------
extern "C" void kernel_launch(void* const* d_in, const int* in_sizes, int n_in,
                              void* d_out, int out_size) {
    const float* x      = (const float*)d_in[0];
    const float* W_re   = (const float*)d_in[1];
    const float* b_re   = (const float*)d_in[2];
    const float* W_rd   = (const float*)d_in[3];
    const float* W_down = (const float*)d_in[4];
    const float* W_up   = (const float*)d_in[5];
    const float* W_ce   = (const float*)d_in[6];
    const float* b_ce   = (const float*)d_in[7];
    const float* W_cd   = (const float*)d_in[8];
    const float* dbias  = (const float*)d_in[9];
    float* out = (float*)d_out;

    k_precompGM<<<dim3(PP, 16), 256>>>(W_down, W_ce, W_up, W_cd, W_rd);  // G+M fused; zeroes g_count
    k_gemm_logits<<<dim3(PP / 64, BB / 64), 256>>>(x, W_re, b_re);
    k_topk<<<(BB * 32) / 256, 256>>>();
    k_childlogits<<<dim3(PP, 2), 256>>>(x, b_ce);                        // <- captured launch #4
    k_decode<<<BB, 256>>>(dbias, out);
}

// round 17
// speedup vs baseline: 1.0707x; 1.0482x over previous
#include <cuda_runtime.h>
#include <math_constants.h>
#include <cstdint>

#define BB 4096
#define DD 2048
#define PP 256
#define SS 64
#define CC 32
#define KP 8
#define BUCKET 256

// ---------------- scratch (device globals; no allocation) ----------------
__device__ float g_logits[BB * PP];                 // 4 MB
__device__ int   g_topidx[BB * KP];
__device__ int   g_child[BB * KP];
__device__ float g_G[(size_t)PP * DD * CC];         // 64 MB  [p][d][c]  (transposed)
__device__ float g_M[(size_t)PP * CC * DD];         // 64 MB  [p][c][d] (+0.1*W_rd col)
__device__ int   g_count[PP];
__device__ int   g_pairs[PP * BUCKET];

// ---------------- parent logits: [B,P] = X @ Wre^T + bre (double-buffered) ----------------
__global__ void __launch_bounds__(256) k_gemm_logits(const float* __restrict__ X,
                                                     const float* __restrict__ Wre,
                                                     const float* __restrict__ bre) {
    __shared__ float As[2][32][68];    // [buf][k][m]
    __shared__ float Bs[2][32][68];    // [buf][k][n]
    const int tid = threadIdx.x;
    const int n0b = blockIdx.x * 64;
    const int m0b = blockIdx.y * 64;
    const int n0 = (tid & 15) * 4;
    const int m0 = (tid >> 4) * 4;
    const int r0 = tid >> 3,          kq0 = tid & 7;
    const int r1 = (tid + 256) >> 3,  kq1 = (tid + 256) & 7;

    float acc[4][4];
#pragma unroll
    for (int i = 0; i < 4; i++)
#pragma unroll
        for (int j = 0; j < 4; j++) acc[i][j] = 0.f;

    {
        float4 a0 = *(const float4*)&X[(size_t)(m0b + r0) * DD + kq0 * 4];
        float4 a1 = *(const float4*)&X[(size_t)(m0b + r1) * DD + kq1 * 4];
        float4 b0 = *(const float4*)&Wre[(size_t)(n0b + r0) * DD + kq0 * 4];
        float4 b1 = *(const float4*)&Wre[(size_t)(n0b + r1) * DD + kq1 * 4];
        As[0][kq0 * 4 + 0][r0] = a0.x; As[0][kq0 * 4 + 1][r0] = a0.y;
        As[0][kq0 * 4 + 2][r0] = a0.z; As[0][kq0 * 4 + 3][r0] = a0.w;
        As[0][kq1 * 4 + 0][r1] = a1.x; As[0][kq1 * 4 + 1][r1] = a1.y;
        As[0][kq1 * 4 + 2][r1] = a1.z; As[0][kq1 * 4 + 3][r1] = a1.w;
        Bs[0][kq0 * 4 + 0][r0] = b0.x; Bs[0][kq0 * 4 + 1][r0] = b0.y;
        Bs[0][kq0 * 4 + 2][r0] = b0.z; Bs[0][kq0 * 4 + 3][r0] = b0.w;
        Bs[0][kq1 * 4 + 0][r1] = b1.x; Bs[0][kq1 * 4 + 1][r1] = b1.y;
        Bs[0][kq1 * 4 + 2][r1] = b1.z; Bs[0][kq1 * 4 + 3][r1] = b1.w;
    }
    __syncthreads();

    int cur = 0;
    for (int k0 = 32; k0 <= DD; k0 += 32) {
        float4 a0, a1, b0, b1;
        const bool more = (k0 < DD);
        if (more) {
            a0 = *(const float4*)&X[(size_t)(m0b + r0) * DD + k0 + kq0 * 4];
            a1 = *(const float4*)&X[(size_t)(m0b + r1) * DD + k0 + kq1 * 4];
            b0 = *(const float4*)&Wre[(size_t)(n0b + r0) * DD + k0 + kq0 * 4];
            b1 = *(const float4*)&Wre[(size_t)(n0b + r1) * DD + k0 + kq1 * 4];
        }
#pragma unroll 8
        for (int k = 0; k < 32; k++) {
            float4 a = *(const float4*)&As[cur][k][m0];
            float4 b = *(const float4*)&Bs[cur][k][n0];
            acc[0][0] += a.x * b.x; acc[0][1] += a.x * b.y; acc[0][2] += a.x * b.z; acc[0][3] += a.x * b.w;
            acc[1][0] += a.y * b.x; acc[1][1] += a.y * b.y; acc[1][2] += a.y * b.z; acc[1][3] += a.y * b.w;
            acc[2][0] += a.z * b.x; acc[2][1] += a.z * b.y; acc[2][2] += a.z * b.z; acc[2][3] += a.z * b.w;
            acc[3][0] += a.w * b.x; acc[3][1] += a.w * b.y; acc[3][2] += a.w * b.z; acc[3][3] += a.w * b.w;
        }
        if (more) {
            int nxt = cur ^ 1;
            As[nxt][kq0 * 4 + 0][r0] = a0.x; As[nxt][kq0 * 4 + 1][r0] = a0.y;
            As[nxt][kq0 * 4 + 2][r0] = a0.z; As[nxt][kq0 * 4 + 3][r0] = a0.w;
            As[nxt][kq1 * 4 + 0][r1] = a1.x; As[nxt][kq1 * 4 + 1][r1] = a1.y;
            As[nxt][kq1 * 4 + 2][r1] = a1.z; As[nxt][kq1 * 4 + 3][r1] = a1.w;
            Bs[nxt][kq0 * 4 + 0][r0] = b0.x; Bs[nxt][kq0 * 4 + 1][r0] = b0.y;
            Bs[nxt][kq0 * 4 + 2][r0] = b0.z; Bs[nxt][kq0 * 4 + 3][r0] = b0.w;
            Bs[nxt][kq1 * 4 + 0][r1] = b1.x; Bs[nxt][kq1 * 4 + 1][r1] = b1.y;
            Bs[nxt][kq1 * 4 + 2][r1] = b1.z; Bs[nxt][kq1 * 4 + 3][r1] = b1.w;
            __syncthreads();
            cur = nxt;
        }
    }
    float4 bv = *(const float4*)&bre[n0b + n0];
#pragma unroll
    for (int i = 0; i < 4; i++) {
        float4 o = make_float4(acc[i][0] + bv.x, acc[i][1] + bv.y,
                               acc[i][2] + bv.z, acc[i][3] + bv.w);
        *(float4*)&g_logits[(size_t)(m0b + m0 + i) * PP + n0b + n0] = o;
    }
}

// ---------------- top-8 per token + direct bucket append ----------------
__global__ void k_topk() {
    int gw = (blockIdx.x * blockDim.x + threadIdx.x) >> 5;
    int lane = threadIdx.x & 31;
    if (gw >= BB) return;
    const float* lg = g_logits + (size_t)gw * PP;
    float v[8];
    int id[8];
#pragma unroll
    for (int j = 0; j < 8; j++) {
        int p = j * 32 + lane;
        v[j] = lg[p];
        id[j] = p;
    }
    for (int it = 0; it < KP; it++) {
        float bv = v[0];
        int bi = id[0];
#pragma unroll
        for (int j = 1; j < 8; j++) {
            if (v[j] > bv || (v[j] == bv && id[j] < bi)) { bv = v[j]; bi = id[j]; }
        }
#pragma unroll
        for (int off = 16; off >= 1; off >>= 1) {
            float ov = __shfl_down_sync(0xffffffffu, bv, off);
            int   oi = __shfl_down_sync(0xffffffffu, bi, off);
            if (ov > bv || (ov == bv && oi < bi)) { bv = ov; bi = oi; }
        }
        bi = __shfl_sync(0xffffffffu, bi, 0);
        if (lane == 0) {
            g_topidx[gw * KP + it] = bi;
            int pos = atomicAdd(&g_count[bi], 1);
            g_pairs[bi * BUCKET + pos] = gw * KP + it;
        }
#pragma unroll
        for (int j = 0; j < 8; j++)
            if (id[j] == bi) v[j] = -CUDART_INF_F;
    }
}

// ---------------- fused precomp: y<8 -> G tile, y>=8 -> M tile ----------------
__global__ void __launch_bounds__(256) k_precompGM(const float* __restrict__ Wdown,
                                                   const float* __restrict__ Wce,
                                                   const float* __restrict__ Wup,
                                                   const float* __restrict__ Wcd,
                                                   const float* __restrict__ Wrd) {
    __shared__ float Wbuf[32][260];   // [s][d]
    __shared__ float Cbuf[32][36];    // [s][c]
    __shared__ float wrs[256];
    const int p = blockIdx.x;
    const int tid = threadIdx.x;
    const int lane = tid & 31;
    const int wid = tid >> 5;
    const int dl = (wid >> 2) * 128 + lane * 4;
    const int c0 = (wid & 3) * 8;

    float acc[4][8];
#pragma unroll
    for (int j = 0; j < 4; j++)
#pragma unroll
        for (int i = 0; i < 8; i++) acc[j][i] = 0.f;

    if (blockIdx.y < 8) {
        const int d0b = blockIdx.y * 256;
        if (blockIdx.y == 0 && tid == 0) g_count[p] = 0;

        for (int s0 = 0; s0 < SS; s0 += 32) {
#pragma unroll
            for (int it = 0; it < 8; it++) {
                int l = tid + it * 256;
                int s = l >> 6, q = l & 63;
                *(float4*)&Wbuf[s][q * 4] =
                    *(const float4*)&Wdown[((size_t)p * SS + s0 + s) * DD + d0b + q * 4];
            }
            {
                int c = tid >> 3, sq = tid & 7;
                float4 v = *(const float4*)&Wce[((size_t)p * CC + c) * SS + s0 + sq * 4];
                Cbuf[sq * 4 + 0][c] = v.x;
                Cbuf[sq * 4 + 1][c] = v.y;
                Cbuf[sq * 4 + 2][c] = v.z;
                Cbuf[sq * 4 + 3][c] = v.w;
            }
            __syncthreads();
#pragma unroll 4
            for (int s = 0; s < 32; s++) {
                float4 w   = *(const float4*)&Wbuf[s][dl];
                float4 cd0 = *(const float4*)&Cbuf[s][c0];
                float4 cd1 = *(const float4*)&Cbuf[s][c0 + 4];
                acc[0][0] += w.x * cd0.x; acc[0][1] += w.x * cd0.y; acc[0][2] += w.x * cd0.z; acc[0][3] += w.x * cd0.w;
                acc[0][4] += w.x * cd1.x; acc[0][5] += w.x * cd1.y; acc[0][6] += w.x * cd1.z; acc[0][7] += w.x * cd1.w;
                acc[1][0] += w.y * cd0.x; acc[1][1] += w.y * cd0.y; acc[1][2] += w.y * cd0.z; acc[1][3] += w.y * cd0.w;
                acc[1][4] += w.y * cd1.x; acc[1][5] += w.y * cd1.y; acc[1][6] += w.y * cd1.z; acc[1][7] += w.y * cd1.w;
                acc[2][0] += w.z * cd0.x; acc[2][1] += w.z * cd0.y; acc[2][2] += w.z * cd0.z; acc[2][3] += w.z * cd0.w;
                acc[2][4] += w.z * cd1.x; acc[2][5] += w.z * cd1.y; acc[2][6] += w.z * cd1.z; acc[2][7] += w.z * cd1.w;
                acc[3][0] += w.w * cd0.x; acc[3][1] += w.w * cd0.y; acc[3][2] += w.w * cd0.z; acc[3][3] += w.w * cd0.w;
                acc[3][4] += w.w * cd1.x; acc[3][5] += w.w * cd1.y; acc[3][6] += w.w * cd1.z; acc[3][7] += w.w * cd1.w;
            }
            __syncthreads();
        }
#pragma unroll
        for (int u = 0; u < 4; u++) {
            size_t row = ((size_t)p * DD + d0b + dl + u) * CC;
            *(float4*)&g_G[row + c0]     = make_float4(acc[u][0], acc[u][1], acc[u][2], acc[u][3]);
            *(float4*)&g_G[row + c0 + 4] = make_float4(acc[u][4], acc[u][5], acc[u][6], acc[u][7]);
        }
    } else {
        const int d0b = (blockIdx.y - 8) * 256;
        wrs[tid] = 0.1f * Wrd[(size_t)(d0b + tid) * PP + p];

        for (int s0 = 0; s0 < SS; s0 += 32) {
#pragma unroll
            for (int it = 0; it < 8; it++) {
                int l = tid + it * 256;
                int d = l >> 3, sq = l & 7;
                float4 v = *(const float4*)&Wup[((size_t)p * DD + d0b + d) * SS + s0 + sq * 4];
                Wbuf[sq * 4 + 0][d] = v.x;
                Wbuf[sq * 4 + 1][d] = v.y;
                Wbuf[sq * 4 + 2][d] = v.z;
                Wbuf[sq * 4 + 3][d] = v.w;
            }
            {
                int s = tid >> 3, q = tid & 7;
                *(float4*)&Cbuf[s][q * 4] =
                    *(const float4*)&Wcd[((size_t)p * SS + s0 + s) * CC + q * 4];
            }
            __syncthreads();
#pragma unroll 4
            for (int s = 0; s < 32; s++) {
                float4 w   = *(const float4*)&Wbuf[s][dl];
                float4 cd0 = *(const float4*)&Cbuf[s][c0];
                float4 cd1 = *(const float4*)&Cbuf[s][c0 + 4];
                acc[0][0] += w.x * cd0.x; acc[0][1] += w.x * cd0.y; acc[0][2] += w.x * cd0.z; acc[0][3] += w.x * cd0.w;
                acc[0][4] += w.x * cd1.x; acc[0][5] += w.x * cd1.y; acc[0][6] += w.x * cd1.z; acc[0][7] += w.x * cd1.w;
                acc[1][0] += w.y * cd0.x; acc[1][1] += w.y * cd0.y; acc[1][2] += w.y * cd0.z; acc[1][3] += w.y * cd0.w;
                acc[1][4] += w.y * cd1.x; acc[1][5] += w.y * cd1.y; acc[1][6] += w.y * cd1.z; acc[1][7] += w.y * cd1.w;
                acc[2][0] += w.z * cd0.x; acc[2][1] += w.z * cd0.y; acc[2][2] += w.z * cd0.z; acc[2][3] += w.z * cd0.w;
                acc[2][4] += w.z * cd1.x; acc[2][5] += w.z * cd1.y; acc[2][6] += w.z * cd1.z; acc[2][7] += w.z * cd1.w;
                acc[3][0] += w.w * cd0.x; acc[3][1] += w.w * cd0.y; acc[3][2] += w.w * cd0.z; acc[3][3] += w.w * cd0.w;
                acc[3][4] += w.w * cd1.x; acc[3][5] += w.w * cd1.y; acc[3][6] += w.w * cd1.z; acc[3][7] += w.w * cd1.w;
            }
            __syncthreads();
        }
#pragma unroll
        for (int i = 0; i < 8; i++) {
            size_t row = ((size_t)p * CC + c0 + i) * DD + d0b + dl;
            *(float4*)&g_M[row] = make_float4(acc[0][i] + wrs[dl + 0], acc[1][i] + wrs[dl + 1],
                                              acc[2][i] + wrs[dl + 2], acc[3][i] + wrs[dl + 3]);
        }
    }
}

// ---------------- per-parent child logits + argmax (G is [p][d][c]) ----------------
// grid (P, 2), 128 threads. tile 64 tok x 32 c; thread: 4 tok (r+16j) x 4 c (qc).
// 32-d chunks, double-buffered smem + register prefetch, one sync per chunk.
__global__ void __launch_bounds__(128) k_childlogits(const float* __restrict__ X,
                                                     const float* __restrict__ bce) {
    __shared__ float Xs[2][64][36];   // [buf][tok][d]
    __shared__ float Gs[2][32][36];   // [buf][d][c]
    __shared__ int toks[64];
    const int p = blockIdx.x;
    const int base = p * BUCKET;
    const int n = g_count[p];
    const int tid = threadIdx.x;
    const int r  = tid >> 3;          // 0..15 : token rows r+16j; G d-rows r, r+16
    const int q  = tid & 7;
    const int qc = q * 4;             // load column offset; also this thread's c0
    float bc[4];
#pragma unroll
    for (int i = 0; i < 4; i++) bc[i] = bce[p * CC + qc + i];

    for (int t0 = blockIdx.y * 64; t0 < n; t0 += 128) {
        if (tid < 64) toks[tid] = (t0 + tid < n) ? g_pairs[base + t0 + tid] : -1;
        __syncthreads();

        float acc[4][4];              // [tok j][c i]
#pragma unroll
        for (int j = 0; j < 4; j++)
#pragma unroll
            for (int i = 0; i < 4; i++) acc[j][i] = 0.f;

        int pi[4];
        const float* xrow[4];
#pragma unroll
        for (int j = 0; j < 4; j++) {
            pi[j] = toks[r + 16 * j];
            xrow[j] = (pi[j] >= 0) ? &X[(size_t)(pi[j] >> 3) * DD] : 0;
        }
        const float* grow = &g_G[((size_t)p * DD + r) * CC + qc];   // +16*CC for row r+16

        // prologue: chunk 0 -> buf 0
        {
            float4 z = make_float4(0.f, 0.f, 0.f, 0.f);
#pragma unroll
            for (int j = 0; j < 4; j++) {
                float4 xa = xrow[j] ? *(const float4*)&xrow[j][qc] : z;
                *(float4*)&Xs[0][r + 16 * j][qc] = xa;
            }
            *(float4*)&Gs[0][r][qc]      = *(const float4*)&grow[0];
            *(float4*)&Gs[0][r + 16][qc] = *(const float4*)&grow[(size_t)16 * CC];
        }
        __syncthreads();

        int cur = 0;
        for (int d0 = 32; d0 <= DD; d0 += 32) {
            float4 xa[4], ga0, ga1;
            const bool more = (d0 < DD);
            if (more) {
                float4 z = make_float4(0.f, 0.f, 0.f, 0.f);
#pragma unroll
                for (int j = 0; j < 4; j++)
                    xa[j] = xrow[j] ? *(const float4*)&xrow[j][d0 + qc] : z;
                ga0 = *(const float4*)&grow[(size_t)d0 * CC];
                ga1 = *(const float4*)&grow[(size_t)(d0 + 16) * CC];
            }
#pragma unroll
            for (int d4 = 0; d4 < 32; d4 += 4) {
                float4 xv[4];
#pragma unroll
                for (int j = 0; j < 4; j++) xv[j] = *(const float4*)&Xs[cur][r + 16 * j][d4];
                float4 g0 = *(const float4*)&Gs[cur][d4 + 0][qc];
                float4 g1 = *(const float4*)&Gs[cur][d4 + 1][qc];
                float4 g2 = *(const float4*)&Gs[cur][d4 + 2][qc];
                float4 g3 = *(const float4*)&Gs[cur][d4 + 3][qc];
#pragma unroll
                for (int j = 0; j < 4; j++) {
                    acc[j][0] += xv[j].x * g0.x + xv[j].y * g1.x + xv[j].z * g2.x + xv[j].w * g3.x;
                    acc[j][1] += xv[j].x * g0.y + xv[j].y * g1.y + xv[j].z * g2.y + xv[j].w * g3.y;
                    acc[j][2] += xv[j].x * g0.z + xv[j].y * g1.z + xv[j].z * g2.z + xv[j].w * g3.z;
                    acc[j][3] += xv[j].x * g0.w + xv[j].y * g1.w + xv[j].z * g2.w + xv[j].w * g3.w;
                }
            }
            if (more) {
                int nxt = cur ^ 1;
#pragma unroll
                for (int j = 0; j < 4; j++)
                    *(float4*)&Xs[nxt][r + 16 * j][qc] = xa[j];
                *(float4*)&Gs[nxt][r][qc]      = ga0;
                *(float4*)&Gs[nxt][r + 16][qc] = ga1;
                __syncthreads();
                cur = nxt;
            }
        }

        // argmax over 32 c per token (tie -> lower index), width-8 shuffle groups
#pragma unroll
        for (int j = 0; j < 4; j++) {
            float bv = acc[j][0] + bc[0];
            int bi = qc;
#pragma unroll
            for (int i = 1; i < 4; i++) {
                float v = acc[j][i] + bc[i];
                if (v > bv) { bv = v; bi = qc + i; }
            }
#pragma unroll
            for (int off = 4; off >= 1; off >>= 1) {
                float ov = __shfl_down_sync(0xffffffffu, bv, off, 8);
                int   oi = __shfl_down_sync(0xffffffffu, bi, off, 8);
                if (ov > bv || (ov == bv && oi < bi)) { bv = ov; bi = oi; }
            }
            if (q == 0) {
                if (pi[j] >= 0) g_child[pi[j]] = bi;
            }
        }
        __syncthreads();   // protect toks/smem before next tile
    }
}

// ---------------- decode: out = bias + sum_k M'[p_k][c_k] ----------------
__global__ void k_decode(const float* __restrict__ dbias, float* __restrict__ out) {
    const int b = blockIdx.x;
    __shared__ int sp[KP], sc[KP];
    const int tid = threadIdx.x;
    if (tid < KP) {
        sp[tid] = g_topidx[b * KP + tid];
        sc[tid] = g_child[b * KP + tid];
    }
    __syncthreads();
    size_t rowbase[KP];
#pragma unroll
    for (int k = 0; k < KP; k++)
        rowbase[k] = ((size_t)sp[k] * CC + sc[k]) * DD;
#pragma unroll
    for (int it = 0; it < 2; it++) {
        int d = (tid + it * 256) * 4;
        float4 a = *(const float4*)&dbias[d];
#pragma unroll
        for (int k = 0; k < KP; k++) {
            float4 m = *(const float4*)&g_M[rowbase[k] + d];
            a.x += m.x; a.y += m.y; a.z += m.z; a.w += m.w;
        }
        *(float4*)&out[(size_t)b * DD + d] = a;
    }
}

// ---------------- launch (childlogits stays at launch #4 -> ncu capture window) ----------------
extern "C" void kernel_launch(void* const* d_in, const int* in_sizes, int n_in,
                              void* d_out, int out_size) {
    const float* x      = (const float*)d_in[0];
    const float* W_re   = (const float*)d_in[1];
    const float* b_re   = (const float*)d_in[2];
    const float* W_rd   = (const float*)d_in[3];
    const float* W_down = (const float*)d_in[4];
    const float* W_up   = (const float*)d_in[5];
    const float* W_ce   = (const float*)d_in[6];
    const float* b_ce   = (const float*)d_in[7];
    const float* W_cd   = (const float*)d_in[8];
    const float* dbias  = (const float*)d_in[9];
    float* out = (float*)d_out;

    k_precompGM<<<dim3(PP, 16), 256>>>(W_down, W_ce, W_up, W_cd, W_rd);  // G+M fused; zeroes g_count
    k_gemm_logits<<<dim3(PP / 64, BB / 64), 256>>>(x, W_re, b_re);
    k_topk<<<(BB * 32) / 256, 256>>>();
    k_childlogits<<<dim3(PP, 2), 128>>>(x, b_ce);                        // <- captured launch #4
    k_decode<<<BB, 256>>>(dbias, out);
}